// round 1
// baseline (speedup 1.0000x reference)
#include <cuda_runtime.h>

#define T_STEPS 2000
#define N_IN    8192
#define N_OUT   4096

// Scratch for lif_input = x @ W^T  (32.8 MB, fits in L2 so the scan kernel
// reads it at L2 latency right after the GEMM writes it).
__device__ float g_lif[(size_t)T_STEPS * N_OUT];

// ---------------------------------------------------------------------------
// GEMM: C[m,n] = sum_k x[m,k] * W[n,k]   (both operands K-major)
// BM=BN=128, BK=16, 256 threads, 8x8 per-thread tile. fp32 FFMA.
// ---------------------------------------------------------------------------
#define BM 128
#define BN 128
#define BK 16
#define TM 8
#define TN 8

__global__ __launch_bounds__(256, 2)
void gemm_xwT(const float* __restrict__ A,   // [2000, 8192]
              const float* __restrict__ B,   // [4096, 8192]
              float* __restrict__ C)         // [2000, 4096]
{
    __shared__ float As[BK][BM + 4];
    __shared__ float Bs[BK][BN + 4];

    const int tid = threadIdx.x;
    const int bm  = blockIdx.y * BM;
    const int bn  = blockIdx.x * BN;
    const int tx  = tid & 15;        // 0..15 -> col group
    const int ty  = tid >> 4;        // 0..15 -> row group

    float acc[TM][TN];
    #pragma unroll
    for (int i = 0; i < TM; i++)
        #pragma unroll
        for (int j = 0; j < TN; j++) acc[i][j] = 0.f;

    for (int k0 = 0; k0 < N_IN; k0 += BK) {
        // Load A tile (transpose into As[k][m]); clamp rows >= 2000
        #pragma unroll
        for (int i = 0; i < 2; i++) {
            int idx = tid + i * 256;            // 0..511
            int r   = idx >> 2;                 // 0..127
            int c4  = (idx & 3) << 2;           // 0,4,8,12
            int gr  = bm + r; if (gr > T_STEPS - 1) gr = T_STEPS - 1;
            float4 v = *reinterpret_cast<const float4*>(
                &A[(size_t)gr * N_IN + k0 + c4]);
            As[c4 + 0][r] = v.x;
            As[c4 + 1][r] = v.y;
            As[c4 + 2][r] = v.z;
            As[c4 + 3][r] = v.w;
        }
        // Load B tile (transpose into Bs[k][n]); N=4096 divides evenly
        #pragma unroll
        for (int i = 0; i < 2; i++) {
            int idx = tid + i * 256;
            int r   = idx >> 2;
            int c4  = (idx & 3) << 2;
            float4 v = *reinterpret_cast<const float4*>(
                &B[(size_t)(bn + r) * N_IN + k0 + c4]);
            Bs[c4 + 0][r] = v.x;
            Bs[c4 + 1][r] = v.y;
            Bs[c4 + 2][r] = v.z;
            Bs[c4 + 3][r] = v.w;
        }
        __syncthreads();

        #pragma unroll
        for (int k = 0; k < BK; k++) {
            float ra[TM], rb[TN];
            #pragma unroll
            for (int i = 0; i < TM; i++) ra[i] = As[k][ty * TM + i];
            #pragma unroll
            for (int j = 0; j < TN; j++) rb[j] = Bs[k][tx * TN + j];
            #pragma unroll
            for (int i = 0; i < TM; i++)
                #pragma unroll
                for (int j = 0; j < TN; j++)
                    acc[i][j] += ra[i] * rb[j];     // FFMA, sequential-k order
        }
        __syncthreads();
    }

    // Store (guard M edge)
    #pragma unroll
    for (int i = 0; i < TM; i++) {
        int gr = bm + ty * TM + i;
        if (gr < T_STEPS) {
            float* dst = &C[(size_t)gr * N_OUT + bn + tx * TN];
            #pragma unroll
            for (int j = 0; j < TN; j += 4) {
                float4 v = make_float4(acc[i][j], acc[i][j+1], acc[i][j+2], acc[i][j+3]);
                *reinterpret_cast<float4*>(dst + j) = v;
            }
        }
    }
}

// ---------------------------------------------------------------------------
// LIF scan: one thread per neuron, sequential over t, 8-deep software
// pipeline on the lif_input column reads (L2-resident).
// Elementwise ops use explicit round-to-nearest intrinsics so they match the
// JAX reference bit-for-bit (no FMA contraction in the recurrence).
// ---------------------------------------------------------------------------
__global__ __launch_bounds__(64)
void lif_scan(const float* __restrict__ vth_p,
              const float* __restrict__ vrest_p,
              const float* __restrict__ vreset_p,
              const float* __restrict__ tref_p,
              const float* __restrict__ tau_p,
              float* __restrict__ out)
{
    const int j = blockIdx.x * blockDim.x + threadIdx.x;
    if (j >= N_OUT) return;

    const float Vth    = vth_p[j];
    const float Vrest  = vrest_p[j];
    const float Vreset = vreset_p[j];
    const float Tref   = tref_p[j];
    const float ktau   = __fmul_rn(0.001f, tau_p[j]);   // DT * tau
    const float DT     = 0.001f;

    float v      = Vrest;
    float refrac = 0.f;

    out[j] = 0.f;   // t = 0 row stays zero

    const float* __restrict__ col = g_lif + j;

    float buf[8], nbuf[8];
    // prime pipeline: t = 1..8
    #pragma unroll
    for (int u = 0; u < 8; u++) buf[u] = col[(size_t)(1 + u) * N_OUT];

    int t = 1;
    for (; t + 8 <= T_STEPS; t += 8) {
        // prefetch next group
        if (t + 16 <= T_STEPS) {
            #pragma unroll
            for (int u = 0; u < 8; u++) nbuf[u] = col[(size_t)(t + 8 + u) * N_OUT];
        }
        #pragma unroll
        for (int u = 0; u < 8; u++) {
            float inp = buf[u];
            // leak: v = v - ktau*(v - Vrest)   (mul then sub, like the reference)
            v = __fsub_rn(v, __fmul_rn(ktau, __fsub_rn(v, Vrest)));
            // integrate when not refractory
            if (refrac == 0.f) v = __fadd_rn(v, inp);
            // refractory countdown
            refrac = (refrac > 0.f) ? __fsub_rn(refrac, DT) : 0.f;
            // spike + reset
            float d = __fsub_rn(v, Vth);
            float spike = (d >= 0.f) ? 1.f : 0.f;
            if (d >= 0.f) { refrac = Tref; v = Vreset; }
            out[(size_t)(t + u) * N_OUT + j] = spike;
        }
        #pragma unroll
        for (int u = 0; u < 8; u++) buf[u] = nbuf[u];
    }
    // tail (t = 1993..1999)
    for (; t < T_STEPS; t++) {
        float inp = col[(size_t)t * N_OUT];
        v = __fsub_rn(v, __fmul_rn(ktau, __fsub_rn(v, Vrest)));
        if (refrac == 0.f) v = __fadd_rn(v, inp);
        refrac = (refrac > 0.f) ? __fsub_rn(refrac, DT) : 0.f;
        float d = __fsub_rn(v, Vth);
        float spike = (d >= 0.f) ? 1.f : 0.f;
        if (d >= 0.f) { refrac = Tref; v = Vreset; }
        out[(size_t)t * N_OUT + j] = spike;
    }
}

extern "C" void kernel_launch(void* const* d_in, const int* in_sizes, int n_in,
                              void* d_out, int out_size)
{
    const float* x      = (const float*)d_in[0];
    const float* weight = (const float*)d_in[1];
    const float* vth    = (const float*)d_in[2];
    const float* vrest  = (const float*)d_in[3];
    const float* vreset = (const float*)d_in[4];
    const float* tref   = (const float*)d_in[5];
    const float* tau    = (const float*)d_in[6];
    float* out = (float*)d_out;

    float* lif;
    cudaGetSymbolAddress((void**)&lif, g_lif);

    dim3 gblock(256);
    dim3 ggrid(N_OUT / BN, (T_STEPS + BM - 1) / BM);   // 32 x 16
    gemm_xwT<<<ggrid, gblock>>>(x, weight, lif);

    lif_scan<<<N_OUT / 64, 64>>>(vth, vrest, vreset, tref, tau, out);
}

// round 2
// speedup vs baseline: 1.0817x; 1.0817x over previous
#include <cuda_runtime.h>

#define T_STEPS 2000
#define N_IN    8192
#define N_OUT   4096

// Scratch for lif_input = x @ W^T (32.8 MB; scan reads it mostly from L2).
__device__ float g_lif[(size_t)T_STEPS * N_OUT];

// ---------------------------------------------------------------------------
// Packed fp32x2 helpers (Blackwell FFMA2 — ptxas never emits this from C++)
// ---------------------------------------------------------------------------
__device__ __forceinline__ unsigned long long pack2_dup(float v) {
    unsigned long long r;
    asm("mov.b64 %0, {%1, %1};" : "=l"(r) : "f"(v));
    return r;
}
__device__ __forceinline__ unsigned long long pack2(float lo, float hi) {
    unsigned long long r;
    asm("mov.b64 %0, {%1, %2};" : "=l"(r) : "f"(lo), "f"(hi));
    return r;
}
__device__ __forceinline__ void unpack2(unsigned long long p, float& lo, float& hi) {
    asm("mov.b64 {%0, %1}, %2;" : "=f"(lo), "=f"(hi) : "l"(p));
}
__device__ __forceinline__ void ffma2(unsigned long long& d,
                                      unsigned long long a,
                                      unsigned long long b) {
    // d = a * b + d, per-lane IEEE fp32 round-to-nearest
    asm("fma.rn.f32x2 %0, %1, %2, %0;" : "+l"(d) : "l"(a), "l"(b));
}

// ---------------------------------------------------------------------------
// GEMM: C[m,n] = sum_k x[m,k] * W[n,k]   (both K-major)
// BM=BN=128, BK=16, 256 threads, 8x8 per-thread tile computed as 8x4 f32x2
// pairs via fma.rn.f32x2. Register-staged global prefetch (single smem buffer).
// ---------------------------------------------------------------------------
#define BM 128
#define BN 128
#define BK 16
#define TM 8
#define TN 8

__global__ __launch_bounds__(256, 2)
void gemm_xwT(const float* __restrict__ A,   // [2000, 8192]
              const float* __restrict__ B,   // [4096, 8192]
              float* __restrict__ C)         // [2000, 4096]
{
    __shared__ float As[BK][BM + 4];
    __shared__ float Bs[BK][BN + 4];

    const int tid = threadIdx.x;
    const int bm  = blockIdx.y * BM;
    const int bn  = blockIdx.x * BN;
    const int tx  = tid & 15;        // 0..15 -> col group
    const int ty  = tid >> 4;        // 0..15 -> row group

    // Global-load geometry (each thread loads 2 float4 per operand per tile)
    const int r0 = tid >> 2;                 // 0..63
    const int r1 = r0 + 64;                  // 64..127
    const int c4 = (tid & 3) << 2;           // 0,4,8,12
    int garow0 = bm + r0; if (garow0 > T_STEPS - 1) garow0 = T_STEPS - 1;
    int garow1 = bm + r1; if (garow1 > T_STEPS - 1) garow1 = T_STEPS - 1;
    const float* Ap0 = A + (size_t)garow0 * N_IN + c4;
    const float* Ap1 = A + (size_t)garow1 * N_IN + c4;
    const float* Bp0 = B + (size_t)(bn + r0) * N_IN + c4;
    const float* Bp1 = B + (size_t)(bn + r1) * N_IN + c4;

    unsigned long long acc2[TM][TN / 2];
    #pragma unroll
    for (int i = 0; i < TM; i++)
        #pragma unroll
        for (int jp = 0; jp < TN / 2; jp++) acc2[i][jp] = 0ull;

    // Prologue: load tile k0 = 0 into registers
    float4 pa0 = *reinterpret_cast<const float4*>(Ap0);
    float4 pa1 = *reinterpret_cast<const float4*>(Ap1);
    float4 pb0 = *reinterpret_cast<const float4*>(Bp0);
    float4 pb1 = *reinterpret_cast<const float4*>(Bp1);

    for (int k0 = 0; k0 < N_IN; k0 += BK) {
        // Commit prefetched tile to smem (transposed to [k][m] / [k][n])
        As[c4 + 0][r0] = pa0.x; As[c4 + 1][r0] = pa0.y;
        As[c4 + 2][r0] = pa0.z; As[c4 + 3][r0] = pa0.w;
        As[c4 + 0][r1] = pa1.x; As[c4 + 1][r1] = pa1.y;
        As[c4 + 2][r1] = pa1.z; As[c4 + 3][r1] = pa1.w;
        Bs[c4 + 0][r0] = pb0.x; Bs[c4 + 1][r0] = pb0.y;
        Bs[c4 + 2][r0] = pb0.z; Bs[c4 + 3][r0] = pb0.w;
        Bs[c4 + 0][r1] = pb1.x; Bs[c4 + 1][r1] = pb1.y;
        Bs[c4 + 2][r1] = pb1.z; Bs[c4 + 3][r1] = pb1.w;
        __syncthreads();

        // Issue next tile's global loads (latency hidden by compute below)
        if (k0 + BK < N_IN) {
            int koff = k0 + BK;
            pa0 = *reinterpret_cast<const float4*>(Ap0 + koff);
            pa1 = *reinterpret_cast<const float4*>(Ap1 + koff);
            pb0 = *reinterpret_cast<const float4*>(Bp0 + koff);
            pb1 = *reinterpret_cast<const float4*>(Bp1 + koff);
        }

        #pragma unroll
        for (int k = 0; k < BK; k++) {
            float ra[TM];
            #pragma unroll
            for (int i = 0; i < TM; i++) ra[i] = As[k][ty * TM + i];

            unsigned long long bb[TN / 2];
            #pragma unroll
            for (int jp = 0; jp < TN / 2; jp++) {
                float2 v = *reinterpret_cast<const float2*>(&Bs[k][tx * TN + 2 * jp]);
                bb[jp] = pack2(v.x, v.y);
            }

            #pragma unroll
            for (int i = 0; i < TM; i++) {
                unsigned long long aa = pack2_dup(ra[i]);
                #pragma unroll
                for (int jp = 0; jp < TN / 2; jp++)
                    ffma2(acc2[i][jp], aa, bb[jp]);
            }
        }
        __syncthreads();
    }

    // Store (guard M edge)
    #pragma unroll
    for (int i = 0; i < TM; i++) {
        int gr = bm + ty * TM + i;
        if (gr < T_STEPS) {
            float* dst = &C[(size_t)gr * N_OUT + bn + tx * TN];
            #pragma unroll
            for (int jp = 0; jp < TN / 2; jp += 2) {
                float4 v;
                unpack2(acc2[i][jp],     v.x, v.y);
                unpack2(acc2[i][jp + 1], v.z, v.w);
                *reinterpret_cast<float4*>(dst + 2 * jp) = v;
            }
        }
    }
}

// ---------------------------------------------------------------------------
// LIF scan: one thread per neuron, sequential over t, 8-deep software
// pipeline on the lif_input column reads (L2-resident). Elementwise ops use
// explicit RN intrinsics to match the JAX reference bit-for-bit.
// ---------------------------------------------------------------------------
__global__ __launch_bounds__(64)
void lif_scan(const float* __restrict__ vth_p,
              const float* __restrict__ vrest_p,
              const float* __restrict__ vreset_p,
              const float* __restrict__ tref_p,
              const float* __restrict__ tau_p,
              float* __restrict__ out)
{
    const int j = blockIdx.x * blockDim.x + threadIdx.x;
    if (j >= N_OUT) return;

    const float Vth    = vth_p[j];
    const float Vrest  = vrest_p[j];
    const float Vreset = vreset_p[j];
    const float Tref   = tref_p[j];
    const float ktau   = __fmul_rn(0.001f, tau_p[j]);   // DT * tau
    const float DT     = 0.001f;

    float v      = Vrest;
    float refrac = 0.f;

    out[j] = 0.f;   // t = 0 row stays zero

    const float* __restrict__ col = g_lif + j;

    float buf[8], nbuf[8];
    #pragma unroll
    for (int u = 0; u < 8; u++) buf[u] = col[(size_t)(1 + u) * N_OUT];

    int t = 1;
    for (; t + 8 <= T_STEPS; t += 8) {
        if (t + 16 <= T_STEPS) {
            #pragma unroll
            for (int u = 0; u < 8; u++) nbuf[u] = col[(size_t)(t + 8 + u) * N_OUT];
        }
        #pragma unroll
        for (int u = 0; u < 8; u++) {
            float inp = buf[u];
            v = __fsub_rn(v, __fmul_rn(ktau, __fsub_rn(v, Vrest)));
            if (refrac == 0.f) v = __fadd_rn(v, inp);
            refrac = (refrac > 0.f) ? __fsub_rn(refrac, DT) : 0.f;
            float d = __fsub_rn(v, Vth);
            float spike = (d >= 0.f) ? 1.f : 0.f;
            if (d >= 0.f) { refrac = Tref; v = Vreset; }
            out[(size_t)(t + u) * N_OUT + j] = spike;
        }
        #pragma unroll
        for (int u = 0; u < 8; u++) buf[u] = nbuf[u];
    }
    for (; t < T_STEPS; t++) {
        float inp = col[(size_t)t * N_OUT];
        v = __fsub_rn(v, __fmul_rn(ktau, __fsub_rn(v, Vrest)));
        if (refrac == 0.f) v = __fadd_rn(v, inp);
        refrac = (refrac > 0.f) ? __fsub_rn(refrac, DT) : 0.f;
        float d = __fsub_rn(v, Vth);
        float spike = (d >= 0.f) ? 1.f : 0.f;
        if (d >= 0.f) { refrac = Tref; v = Vreset; }
        out[(size_t)t * N_OUT + j] = spike;
    }
}

extern "C" void kernel_launch(void* const* d_in, const int* in_sizes, int n_in,
                              void* d_out, int out_size)
{
    const float* x      = (const float*)d_in[0];
    const float* weight = (const float*)d_in[1];
    const float* vth    = (const float*)d_in[2];
    const float* vrest  = (const float*)d_in[3];
    const float* vreset = (const float*)d_in[4];
    const float* tref   = (const float*)d_in[5];
    const float* tau    = (const float*)d_in[6];
    float* out = (float*)d_out;

    float* lif;
    cudaGetSymbolAddress((void**)&lif, g_lif);

    dim3 gblock(256);
    dim3 ggrid(N_OUT / BN, (T_STEPS + BM - 1) / BM);   // 32 x 16
    gemm_xwT<<<ggrid, gblock>>>(x, weight, lif);

    lif_scan<<<N_OUT / 64, 64>>>(vth, vrest, vreset, tref, tau, out);
}

// round 8
// speedup vs baseline: 1.1268x; 1.0417x over previous
#include <cuda_runtime.h>
#include <cstdint>

#define T_STEPS    2000
#define LIF_STRIDE 2048
#define N_IN       8192
#define N_OUT      4096

// lif_input stored NEURON-MAJOR: g_lif[n * 2048 + t]
__device__ float g_lif[(size_t)N_OUT * LIF_STRIDE];

// ---------------------------------------------------------------------------
// FFMA2: d = a*b + d per 32-bit half, IEEE fp32 RN — bit-identical to two
// independent scalar FFMA chains. (Blackwell f32x2; ptxas won't emit from C++.)
// ---------------------------------------------------------------------------
__device__ __forceinline__ void ffma2(unsigned long long& d,
                                      unsigned long long a,
                                      unsigned long long b) {
    asm("fma.rn.f32x2 %0, %1, %2, %0;" : "+l"(d) : "l"(a), "l"(b));
}

// ---------------------------------------------------------------------------
// GEMM: lif[n][m] = sum_k A[m,k] * W[n,k], pure fp32, ascending-k FMA chain
// per output element (bit-identical to the reference reduction order).
// Tile 128(M) x 256(N), BK=16, 256 threads, per-thread 8x16 via 64 FFMA2/k.
// smem holds A pre-DUPLICATED ({a,a} u64) and B pre-PAIRED ({b0,b1} u64):
// every inner-loop operand is one LDS.64, zero packing MOVs.
// ---------------------------------------------------------------------------
#define BM 128
#define BN 256
#define BK 16
#define NCHUNKS (N_IN / BK)          // 512
#define STAGE_BYTES 32768            // As2 16KB + Bs2 16KB
#define SMEM_TOTAL  (2 * STAGE_BYTES)
#define OFF_B 16384

struct LdRegs { float4 a[2]; float4 b[4]; };

__device__ __forceinline__ void ldg_chunk(const float* __restrict__ A,
                                          const float* __restrict__ B,
                                          int bm, int bn, int k0, int tid,
                                          LdRegs& r) {
    // A: row = tid/2 (0..127), k-offset = (tid&1)*8 (two float4, 32B contiguous)
    int ar = bm + (tid >> 1); if (ar > T_STEPS - 1) ar = T_STEPS - 1;
    int ko = (tid & 1) * 8;
    const float* ap = &A[(size_t)ar * N_IN + k0 + ko];
    r.a[0] = *reinterpret_cast<const float4*>(ap);
    r.a[1] = *reinterpret_cast<const float4*>(ap + 4);
    // B: pair p = tid/2 (0..127) -> rows bn+2p, bn+2p+1; same 32B k-window
    int p = tid >> 1;
    const float* bp0 = &B[(size_t)(bn + 2 * p) * N_IN + k0 + ko];
    const float* bp1 = &B[(size_t)(bn + 2 * p + 1) * N_IN + k0 + ko];
    r.b[0] = *reinterpret_cast<const float4*>(bp0);
    r.b[1] = *reinterpret_cast<const float4*>(bp0 + 4);
    r.b[2] = *reinterpret_cast<const float4*>(bp1);
    r.b[3] = *reinterpret_cast<const float4*>(bp1 + 4);
}

__device__ __forceinline__ void sts_chunk(char* stage, int tid, const LdRegs& r) {
    int row = tid >> 1;              // A row / B pair index
    int ko  = (tid & 1) * 8;         // k offset of this thread's 8 k-values
    const float* av  = (const float*)&r.a[0];   // 8 floats, k ascending
    const float* bv0 = (const float*)&r.b[0];   // row 2p,  8 floats
    const float* bv1 = (const float*)&r.b[2];   // row 2p+1, 8 floats
    #pragma unroll
    for (int e = 0; e < 8; e++) {
        int k = ko + e;
        float a = av[e];
        float2 da = make_float2(a, a);
        *reinterpret_cast<float2*>(stage + (size_t)k * 1024 + row * 8) = da;
        float2 db = make_float2(bv0[e], bv1[e]);
        *reinterpret_cast<float2*>(stage + OFF_B + (size_t)k * 1024 + row * 8) = db;
    }
}

__global__ __launch_bounds__(256, 1)
void gemm_ffma2(const float* __restrict__ A,   // [2000, 8192]
                const float* __restrict__ B)   // [4096, 8192]
{
    extern __shared__ char smem[];
    const int tid = threadIdx.x;
    const int tx  = tid & 15;        // n group
    const int ty  = tid >> 4;        // m group
    const int bm  = blockIdx.y * BM;
    const int bn  = blockIdx.x * BN;

    unsigned long long acc[8][8];    // [m][n-pair], halves = (n_even, n_odd)
    #pragma unroll
    for (int i = 0; i < 8; i++)
        #pragma unroll
        for (int j = 0; j < 8; j++) acc[i][j] = 0ull;

    LdRegs regs;
    ldg_chunk(A, B, bm, bn, 0, tid, regs);

    for (int c = 0; c < NCHUNKS; c++) {
        char* stage = smem + (c & 1) * STAGE_BYTES;
        sts_chunk(stage, tid, regs);
        __syncthreads();
        if (c + 1 < NCHUNKS) ldg_chunk(A, B, bm, bn, (c + 1) * BK, tid, regs);

        const char* sA = stage;
        const char* sB = stage + OFF_B;
        #pragma unroll
        for (int k = 0; k < BK; k++) {
            unsigned long long ra[8], bb[8];
            #pragma unroll
            for (int i = 0; i < 8; i++)
                ra[i] = *reinterpret_cast<const unsigned long long*>(
                    sA + (size_t)k * 1024 + (ty * 8 + i) * 8);
            #pragma unroll
            for (int j = 0; j < 8; j++)
                bb[j] = *reinterpret_cast<const unsigned long long*>(
                    sB + (size_t)k * 1024 + (tx + 16 * j) * 8);
            #pragma unroll
            for (int i = 0; i < 8; i++)
                #pragma unroll
                for (int j = 0; j < 8; j++)
                    ffma2(acc[i][j], ra[i], bb[j]);
        }
        // Safety: a thread entering iteration c+1 writes the other stage only
        // after passing THIS iteration's barrier, which all threads reach only
        // after finishing iteration c-1's reads of that stage (program order).
    }

    // Epilogue: scatter transposed into neuron-major g_lif[n][m]
    #pragma unroll
    for (int i = 0; i < 8; i++) {
        int m = bm + ty * 8 + i;
        if (m < T_STEPS) {
            #pragma unroll
            for (int j = 0; j < 8; j++) {
                int n0 = bn + 2 * (tx + 16 * j);
                float lo = __uint_as_float((uint32_t)(acc[i][j] & 0xFFFFFFFFull));
                float hi = __uint_as_float((uint32_t)(acc[i][j] >> 32));
                g_lif[(size_t)n0 * LIF_STRIDE + m]       = lo;
                g_lif[(size_t)(n0 + 1) * LIF_STRIDE + m] = hi;
            }
        }
    }
}

// ---------------------------------------------------------------------------
// LIF scan: neuron-major streaming input, float4 loads, 4-block prefetch.
// Elementwise ops match the JAX reference bit-for-bit.
// ---------------------------------------------------------------------------
__global__ __launch_bounds__(32)
void lif_scan(const float* __restrict__ vth_p,
              const float* __restrict__ vrest_p,
              const float* __restrict__ vreset_p,
              const float* __restrict__ tref_p,
              const float* __restrict__ tau_p,
              float* __restrict__ out)
{
    const int j = blockIdx.x * 32 + threadIdx.x;

    const float Vth    = vth_p[j];
    const float Vrest  = vrest_p[j];
    const float Vreset = vreset_p[j];
    const float Tref   = tref_p[j];
    const float ktau   = __fmul_rn(0.001f, tau_p[j]);
    const float DT     = 0.001f;

    float v = Vrest, refrac = 0.f;
    out[j] = 0.f;   // t = 0 row

    const float* __restrict__ row = g_lif + (size_t)j * LIF_STRIDE;
    const int NBLK = T_STEPS / 8;   // 250

    float4 pf[8];
    #pragma unroll
    for (int b = 0; b < 4; b++) {
        pf[2 * b]     = *reinterpret_cast<const float4*>(row + 8 * b);
        pf[2 * b + 1] = *reinterpret_cast<const float4*>(row + 8 * b + 4);
    }

    for (int b = 0; b < NBLK; b++) {
        int slot = (b & 3) * 2;
        float vals[8];
        vals[0] = pf[slot].x;   vals[1] = pf[slot].y;
        vals[2] = pf[slot].z;   vals[3] = pf[slot].w;
        vals[4] = pf[slot+1].x; vals[5] = pf[slot+1].y;
        vals[6] = pf[slot+1].z; vals[7] = pf[slot+1].w;
        if (b + 4 < NBLK) {
            pf[slot]     = *reinterpret_cast<const float4*>(row + 8 * (b + 4));
            pf[slot + 1] = *reinterpret_cast<const float4*>(row + 8 * (b + 4) + 4);
        }
        #pragma unroll
        for (int u = 0; u < 8; u++) {
            int t = 8 * b + u;
            if (t == 0) continue;
            float inp = vals[u];
            v = __fsub_rn(v, __fmul_rn(ktau, __fsub_rn(v, Vrest)));
            if (refrac == 0.f) v = __fadd_rn(v, inp);
            refrac = (refrac > 0.f) ? __fsub_rn(refrac, DT) : 0.f;
            float d = __fsub_rn(v, Vth);
            float spike = (d >= 0.f) ? 1.f : 0.f;
            if (d >= 0.f) { refrac = Tref; v = Vreset; }
            out[(size_t)t * N_OUT + j] = spike;
        }
    }
}

// ===========================================================================
extern "C" void kernel_launch(void* const* d_in, const int* in_sizes, int n_in,
                              void* d_out, int out_size)
{
    const float* x      = (const float*)d_in[0];
    const float* weight = (const float*)d_in[1];
    const float* vth    = (const float*)d_in[2];
    const float* vrest  = (const float*)d_in[3];
    const float* vreset = (const float*)d_in[4];
    const float* tref   = (const float*)d_in[5];
    const float* tau    = (const float*)d_in[6];
    float* out = (float*)d_out;

    cudaFuncSetAttribute(gemm_ffma2,
                         cudaFuncAttributeMaxDynamicSharedMemorySize, SMEM_TOTAL);

    dim3 ggrid(N_OUT / BN, (T_STEPS + BM - 1) / BM);   // 16 x 16 = 256 CTAs
    gemm_ffma2<<<ggrid, 256, SMEM_TOTAL>>>(x, weight);

    lif_scan<<<N_OUT / 32, 32>>>(vth, vrest, vreset, tref, tau, out);
}